// round 5
// baseline (speedup 1.0000x reference)
#include <cuda_runtime.h>
#include <cuda_fp16.h>
#include <cstdint>

#define BB 32
#define NN 1024
#define DD 512
#define LN_EPS 1e-5f

// ---------------- scratch ----------------
__device__ float  g_denom[BB * NN];
__device__ float  g_colsum[BB * NN];
__device__ float  g_x[BB * NN * DD];
__device__ __align__(256) int8_t g_adj0[(size_t)BB * NN * NN];
__device__ __align__(256) int8_t g_adj1[(size_t)BB * NN * NN];
__device__ __align__(256) int8_t g_xT0[(size_t)BB * DD * NN];
__device__ __align__(256) int8_t g_xT1[(size_t)BB * DD * NN];
__device__ __half g_y_h[(size_t)BB * NN * DD];
__device__ __half g_y_l[(size_t)BB * NN * DD];
__device__ __half g_W0_h[DD * DD];
__device__ __half g_W0_l[DD * DD];
__device__ __half g_W1_h[DD * DD];
__device__ __half g_W1_l[DD * DD];
__device__ unsigned g_amaxA[BB];   // per-batch |adj| max (float bits)
__device__ unsigned g_amaxX[1];    // |x| max (float bits)

// ---------------- PTX helpers ----------------
__device__ __forceinline__ uint32_t smem_u32(const void* p) {
    uint32_t a;
    asm("{ .reg .u64 t; cvta.to.shared.u64 t, %1; cvt.u32.u64 %0, t; }" : "=r"(a) : "l"(p));
    return a;
}
__device__ __forceinline__ void cp_async16(uint32_t dst, const void* src) {
    asm volatile("cp.async.cg.shared.global [%0], [%1], 16;" :: "r"(dst), "l"(src));
}
__device__ __forceinline__ void cp_commit() { asm volatile("cp.async.commit_group;" ::: "memory"); }
template <int N>
__device__ __forceinline__ void cp_wait() { asm volatile("cp.async.wait_group %0;" :: "n"(N) : "memory"); }

__device__ __forceinline__ void ldsm4(uint32_t* r, uint32_t addr) {
    asm volatile("ldmatrix.sync.aligned.m8n8.x4.shared.b16 {%0,%1,%2,%3}, [%4];"
                 : "=r"(r[0]), "=r"(r[1]), "=r"(r[2]), "=r"(r[3]) : "r"(addr));
}
__device__ __forceinline__ void mma16816(float* c, const uint32_t* a, const uint32_t* b) {
    asm volatile("mma.sync.aligned.m16n8k16.row.col.f32.f16.f16.f32 "
                 "{%0,%1,%2,%3}, {%4,%5,%6,%7}, {%8,%9}, {%0,%1,%2,%3};"
                 : "+f"(c[0]), "+f"(c[1]), "+f"(c[2]), "+f"(c[3])
                 : "r"(a[0]), "r"(a[1]), "r"(a[2]), "r"(a[3]), "r"(b[0]), "r"(b[1]));
}
__device__ __forceinline__ void imma16832(int* c, const uint32_t* a, const uint32_t* b) {
    asm volatile("mma.sync.aligned.m16n8k32.row.col.s32.s8.s8.s32 "
                 "{%0,%1,%2,%3}, {%4,%5,%6,%7}, {%8,%9}, {%0,%1,%2,%3};"
                 : "+r"(c[0]), "+r"(c[1]), "+r"(c[2]), "+r"(c[3])
                 : "r"(a[0]), "r"(a[1]), "r"(a[2]), "r"(a[3]), "r"(b[0]), "r"(b[1]));
}

// ---------------- reductions ----------------
__device__ __forceinline__ float block_reduce_sum(float v, float* sh) {
    __syncthreads();
    int tid = threadIdx.x;
    #pragma unroll
    for (int o = 16; o > 0; o >>= 1) v += __shfl_down_sync(0xffffffff, v, o);
    if ((tid & 31) == 0) sh[tid >> 5] = v;
    __syncthreads();
    if (tid < 32) {
        v = (tid < (int)(blockDim.x >> 5)) ? sh[tid] : 0.0f;
        #pragma unroll
        for (int o = 16; o > 0; o >>= 1) v += __shfl_down_sync(0xffffffff, v, o);
        if (tid == 0) sh[0] = v;
    }
    __syncthreads();
    return sh[0];
}

// ---------------- zero colsum + scale scalars ----------------
__global__ void zero2_kernel(float* __restrict__ cs, unsigned* __restrict__ sa,
                             unsigned* __restrict__ sx) {
    int i = blockIdx.x * blockDim.x + threadIdx.x;
    if (i < BB * NN) cs[i] = 0.0f;
    if (i < BB) sa[i] = 0u;
    if (i == 0) sx[0] = 0u;
}
__global__ void zerou_kernel(unsigned* __restrict__ p) { p[0] = 0u; }

// ---------------- adj stats: rowsum->denom, colsum, per-batch absmax ----------------
__global__ void __launch_bounds__(256)
adj_stats_kernel(const float* __restrict__ adj, float* __restrict__ denom,
                 float* __restrict__ colsum, unsigned* __restrict__ amaxA) {
    __shared__ float rowacc[128];
    __shared__ float shm[32];
    const int b = blockIdx.y;
    const int r0 = blockIdx.x * 128;
    const int tid = threadIdx.x;
    const int lane = tid & 31;
    const int col0 = tid * 4;

    for (int i = tid; i < 128; i += 256) rowacc[i] = 0.0f;
    __syncthreads();

    const float* src = adj + (size_t)b * NN * NN + (size_t)r0 * NN;
    float cs0 = 0.f, cs1 = 0.f, cs2 = 0.f, cs3 = 0.f, vmax = 0.f;

    for (int r = 0; r < 128; r++) {
        float4 v = *reinterpret_cast<const float4*>(&src[(size_t)r * NN + col0]);
        cs0 += v.x; cs1 += v.y; cs2 += v.z; cs3 += v.w;
        vmax = fmaxf(vmax, fmaxf(fmaxf(fabsf(v.x), fabsf(v.y)), fmaxf(fabsf(v.z), fabsf(v.w))));
        float s = (v.x + v.y) + (v.z + v.w);
        #pragma unroll
        for (int o = 16; o > 0; o >>= 1) s += __shfl_down_sync(0xffffffff, s, o);
        if (lane == 0) atomicAdd(&rowacc[r], s);
    }
    __syncthreads();
    if (tid < 128) denom[(size_t)b * NN + r0 + tid] = rowacc[tid] + 1.0f;
    float* cdst = colsum + (size_t)b * NN + col0;
    atomicAdd(cdst + 0, cs0);
    atomicAdd(cdst + 1, cs1);
    atomicAdd(cdst + 2, cs2);
    atomicAdd(cdst + 3, cs3);
    // block max -> atomic
    #pragma unroll
    for (int o = 16; o > 0; o >>= 1) vmax = fmaxf(vmax, __shfl_down_sync(0xffffffff, vmax, o));
    if (lane == 0) shm[tid >> 5] = vmax;
    __syncthreads();
    if (tid < 32) {
        float m = (tid < 8) ? shm[tid] : 0.0f;
        #pragma unroll
        for (int o = 16; o > 0; o >>= 1) m = fmaxf(m, __shfl_down_sync(0xffffffff, m, o));
        if (tid == 0) atomicMax(&amaxA[b], __float_as_uint(m));  // m >= 0
    }
}

// ---------------- adj quant: fp32 -> 2x int8 digits ----------------
__global__ void __launch_bounds__(256)
adj_quant_kernel(const float* __restrict__ adj, const unsigned* __restrict__ amaxA,
                 int8_t* __restrict__ A0, int8_t* __restrict__ A1) {
    const int b = blockIdx.y;
    const int r0 = blockIdx.x * 128;
    const int tid = threadIdx.x;
    const int col0 = tid * 4;
    float am = __uint_as_float(amaxA[b]);
    float inv = (am > 0.0f) ? (127.0f / am) : 0.0f;

    const float* src = adj + (size_t)b * NN * NN + (size_t)r0 * NN;
    int8_t* d0 = A0 + (size_t)b * NN * NN + (size_t)r0 * NN;
    int8_t* d1 = A1 + (size_t)b * NN * NN + (size_t)r0 * NN;

    for (int r = 0; r < 128; r++) {
        float4 v = *reinterpret_cast<const float4*>(&src[(size_t)r * NN + col0]);
        float t0 = v.x * inv, t1 = v.y * inv, t2 = v.z * inv, t3 = v.w * inv;
        int q0 = __float2int_rn(t0), q1 = __float2int_rn(t1);
        int q2 = __float2int_rn(t2), q3 = __float2int_rn(t3);
        int s0 = __float2int_rn((t0 - q0) * 128.0f);
        int s1 = __float2int_rn((t1 - q1) * 128.0f);
        int s2 = __float2int_rn((t2 - q2) * 128.0f);
        int s3 = __float2int_rn((t3 - q3) * 128.0f);
        *reinterpret_cast<char4*>(&d0[(size_t)r * NN + col0]) =
            make_char4((char)q0, (char)q1, (char)q2, (char)q3);
        *reinterpret_cast<char4*>(&d1[(size_t)r * NN + col0]) =
            make_char4((char)s0, (char)s1, (char)s2, (char)s3);
    }
}

// ---------------- absmax over fp32 tensor ----------------
__global__ void absmax_kernel(const float* __restrict__ x, int n4, unsigned* __restrict__ out) {
    __shared__ float shm[32];
    float m = 0.0f;
    for (int i = blockIdx.x * blockDim.x + threadIdx.x; i < n4; i += gridDim.x * blockDim.x) {
        float4 v = reinterpret_cast<const float4*>(x)[i];
        m = fmaxf(m, fmaxf(fmaxf(fabsf(v.x), fabsf(v.y)), fmaxf(fabsf(v.z), fabsf(v.w))));
    }
    int tid = threadIdx.x, lane = tid & 31;
    #pragma unroll
    for (int o = 16; o > 0; o >>= 1) m = fmaxf(m, __shfl_down_sync(0xffffffff, m, o));
    if (lane == 0) shm[tid >> 5] = m;
    __syncthreads();
    if (tid < 32) {
        m = (tid < (int)(blockDim.x >> 5)) ? shm[tid] : 0.0f;
        #pragma unroll
        for (int o = 16; o > 0; o >>= 1) m = fmaxf(m, __shfl_down_sync(0xffffffff, m, o));
        if (tid == 0) atomicMax(out, __float_as_uint(m));
    }
}

// ---------------- x[b][m][d] fp32 -> xT digits int8 [b][d][m] ----------------
__global__ void transpose_quant(const float* __restrict__ x, const unsigned* __restrict__ amaxX,
                                int8_t* __restrict__ T0, int8_t* __restrict__ T1) {
    __shared__ float tile[32][33];
    int b = blockIdx.z;
    int m0 = blockIdx.y * 32, d0 = blockIdx.x * 32;
    const float* src = x + (size_t)b * NN * DD;
    int tx = threadIdx.x, ty = threadIdx.y;
    #pragma unroll
    for (int j = 0; j < 32; j += 8)
        tile[ty + j][tx] = src[(size_t)(m0 + ty + j) * DD + d0 + tx];
    __syncthreads();
    float am = __uint_as_float(amaxX[0]);
    float inv = (am > 0.0f) ? (127.0f / am) : 0.0f;
    int tid = ty * 32 + tx;
    int dl = tid >> 3;           // 0..31
    int ml = (tid & 7) * 4;      // 0,4,...28
    char q[4], s[4];
    #pragma unroll
    for (int i = 0; i < 4; i++) {
        float t = tile[ml + i][dl] * inv;
        int a0 = __float2int_rn(t);
        int a1 = __float2int_rn((t - a0) * 128.0f);
        q[i] = (char)a0; s[i] = (char)a1;
    }
    size_t off = (size_t)b * DD * NN + (size_t)(d0 + dl) * NN + m0 + ml;
    *reinterpret_cast<char4*>(&T0[off]) = make_char4(q[0], q[1], q[2], q[3]);
    *reinterpret_cast<char4*>(&T1[off]) = make_char4(s[0], s[1], s[2], s[3]);
}

// ---------------- fp32 -> fp16 hi/lo split (weights) ----------------
__global__ void split_kernel(const float* __restrict__ src, __half* __restrict__ h,
                             __half* __restrict__ l, int n4) {
    int i = blockIdx.x * blockDim.x + threadIdx.x;
    if (i >= n4) return;
    float4 v = reinterpret_cast<const float4*>(src)[i];
    __half h0 = __float2half_rn(v.x), h1 = __float2half_rn(v.y);
    __half h2 = __float2half_rn(v.z), h3 = __float2half_rn(v.w);
    __half l0 = __float2half_rn(v.x - __half2float(h0));
    __half l1 = __float2half_rn(v.y - __half2float(h1));
    __half l2 = __float2half_rn(v.z - __half2float(h2));
    __half l3 = __float2half_rn(v.w - __half2float(h3));
    reinterpret_cast<__half2*>(h)[i * 2 + 0] = __halves2half2(h0, h1);
    reinterpret_cast<__half2*>(h)[i * 2 + 1] = __halves2half2(h2, h3);
    reinterpret_cast<__half2*>(l)[i * 2 + 0] = __halves2half2(l0, l1);
    reinterpret_cast<__half2*>(l)[i * 2 + 1] = __halves2half2(l2, l3);
}

// ================= GEMM1 (int8 IMMA): Y = adj@x + x =================
// A digits [b][m][k] (k=node, 1024), B digits xT [b][d][m].
// D = Sa*Sx*(acc0 + acc1/128); epilogue adds X, splits to fp16 h/l.
#define I8_TB 16384                 // 128 rows x 128 bytes
#define I8_STAGE (4 * I8_TB)        // A0 A1 B0 B1
#define I8_SMEM (2 * I8_STAGE)      // 128 KB

__global__ void __launch_bounds__(256, 1)
gemm1_i8(const int8_t* __restrict__ A0, const int8_t* __restrict__ A1,
         const int8_t* __restrict__ B0, const int8_t* __restrict__ B1,
         const float* __restrict__ Xadd, __half* __restrict__ OutH, __half* __restrict__ OutL,
         const unsigned* __restrict__ amaxA, const unsigned* __restrict__ amaxX) {
    extern __shared__ char smem[];
    const uint32_t sb = smem_u32(smem);
    const int tid = threadIdx.x;
    const int wid = tid >> 5;
    const int lane = tid & 31;
    const int b = blockIdx.z;

    const size_t aOff = (size_t)b * NN * NN + (size_t)(blockIdx.y * 128) * NN;
    const size_t bOff = (size_t)b * DD * NN + (size_t)(blockIdx.x * 128) * NN;
    const long outRow0 = (long)b * NN + blockIdx.y * 128;
    const int colBlk = blockIdx.x * 128;

    const int m0 = (wid >> 2) * 64;
    const int n0 = (wid & 3) * 32;
    const int ltile = lane >> 3;
    const int rowInTile = (lane & 7) + ((ltile & 1) << 3);
    const int kk = ltile >> 1;
    const int lx = lane & 7;

    int acc0[4][4][4], acc1[4][4][4];
    #pragma unroll
    for (int a = 0; a < 4; a++)
        #pragma unroll
        for (int c = 0; c < 4; c++)
            #pragma unroll
            for (int e = 0; e < 4; e++) { acc0[a][c][e] = 0; acc1[a][c][e] = 0; }

    const int8_t* bases[4] = {A0 + aOff, A1 + aOff, B0 + bOff, B1 + bOff};

    auto issue = [&](int i) {
        const uint32_t stg = sb + (uint32_t)(i & 1) * I8_STAGE;
        const int k0 = i * 128;
        #pragma unroll
        for (int t = 0; t < 4; t++) {
            #pragma unroll
            for (int jj = 0; jj < 4; jj++) {
                int cid = tid + jj * 256;
                int row = cid >> 3, c = cid & 7;
                cp_async16(stg + t * I8_TB + row * 128 + ((c ^ (row & 7)) << 4),
                           bases[t] + (size_t)row * NN + k0 + c * 16);
            }
        }
        cp_commit();
    };

    issue(0);
    const int nk = NN / 128;   // 8

    for (int i = 0; i < nk; i++) {
        if (i + 1 < nk) issue(i + 1);
        if (i + 1 < nk) cp_wait<1>(); else cp_wait<0>();
        __syncthreads();

        const uint32_t stg = sb + (uint32_t)(i & 1) * I8_STAGE;
        const uint32_t sA0 = stg, sA1 = stg + I8_TB, sB0 = stg + 2 * I8_TB, sB1 = stg + 3 * I8_TB;

        #pragma unroll
        for (int ks = 0; ks < 4; ks++) {         // k32 steps within 128-byte chunk
            const uint32_t swz = (uint32_t)(((ks * 2 + kk) ^ lx) << 4);
            uint32_t a0f[4][4], a1f[4][4], b0f[4][2], b1f[4][2];
            #pragma unroll
            for (int mf = 0; mf < 4; mf++) {
                uint32_t off = (uint32_t)((m0 + mf * 16 + rowInTile) * 128) + swz;
                ldsm4(a0f[mf], sA0 + off);
                ldsm4(a1f[mf], sA1 + off);
            }
            #pragma unroll
            for (int nh = 0; nh < 2; nh++) {
                uint32_t off = (uint32_t)((n0 + nh * 16 + rowInTile) * 128) + swz;
                uint32_t r[4], s[4];
                ldsm4(r, sB0 + off);
                ldsm4(s, sB1 + off);
                b0f[nh * 2][0] = r[0]; b0f[nh * 2][1] = r[2];
                b0f[nh * 2 + 1][0] = r[1]; b0f[nh * 2 + 1][1] = r[3];
                b1f[nh * 2][0] = s[0]; b1f[nh * 2][1] = s[2];
                b1f[nh * 2 + 1][0] = s[1]; b1f[nh * 2 + 1][1] = s[3];
            }
            #pragma unroll
            for (int mf = 0; mf < 4; mf++)
                #pragma unroll
                for (int nf = 0; nf < 4; nf++)
                    imma16832(acc0[mf][nf], a0f[mf], b0f[nf]);
            #pragma unroll
            for (int mf = 0; mf < 4; mf++)
                #pragma unroll
                for (int nf = 0; nf < 4; nf++)
                    imma16832(acc1[mf][nf], a0f[mf], b1f[nf]);
            #pragma unroll
            for (int mf = 0; mf < 4; mf++)
                #pragma unroll
                for (int nf = 0; nf < 4; nf++)
                    imma16832(acc1[mf][nf], a1f[mf], b0f[nf]);
        }
        __syncthreads();
    }

    // epilogue: float = Sa*Sx*(acc0 + acc1/128) + X -> fp16 hi/lo
    const float sA = __uint_as_float(amaxA[b]) * (1.0f / 127.0f);
    const float sX = __uint_as_float(amaxX[0]) * (1.0f / 127.0f);
    const float sc = sA * sX;
    const int rr = lane >> 2;
    const int cc = (lane & 3) * 2;
    #pragma unroll
    for (int mf = 0; mf < 4; mf++) {
        #pragma unroll
        for (int hf = 0; hf < 2; hf++) {
            long grow = outRow0 + m0 + mf * 16 + rr + hf * 8;
            #pragma unroll
            for (int nf = 0; nf < 4; nf++) {
                int gcol = colBlk + n0 + nf * 8 + cc;
                size_t gi = (size_t)grow * DD + gcol;
                float v0 = sc * ((float)acc0[mf][nf][hf * 2 + 0] + 0.0078125f * (float)acc1[mf][nf][hf * 2 + 0]);
                float v1 = sc * ((float)acc0[mf][nf][hf * 2 + 1] + 0.0078125f * (float)acc1[mf][nf][hf * 2 + 1]);
                float2 xv = *reinterpret_cast<const float2*>(&Xadd[gi]);
                v0 += xv.x; v1 += xv.y;
                __half h0 = __float2half_rn(v0), h1 = __float2half_rn(v1);
                __half l0 = __float2half_rn(v0 - __half2float(h0));
                __half l1 = __float2half_rn(v1 - __half2float(h1));
                *reinterpret_cast<__half2*>(&OutH[gi]) = __halves2half2(h0, h1);
                *reinterpret_cast<__half2*>(&OutL[gi]) = __halves2half2(l0, l1);
            }
        }
    }
}

// ================= GEMM2 (fp16 3-term): X' = relu((Y@W^T + 2b)/denom) ==========
#define KT 64
#define TBYTES 16384
#define STAGE_BYTES (4 * TBYTES)
#define GEMM_SMEM (2 * STAGE_BYTES)

__global__ void __launch_bounds__(256, 1)
gemm2_hmma(const __half* __restrict__ Ah, const __half* __restrict__ Al,
           const __half* __restrict__ Bh, const __half* __restrict__ Bl,
           const float* __restrict__ bias, const float* __restrict__ denom,
           float* __restrict__ OutF) {
    extern __shared__ char smem[];
    const uint32_t sb = smem_u32(smem);
    const int tid = threadIdx.x;
    const int wid = tid >> 5;
    const int lane = tid & 31;

    const long aRow0 = (long)blockIdx.y * 128;
    const long bRow0 = (long)blockIdx.x * 128;
    const int colBlk = blockIdx.x * 128;

    const __half* srcA_h = Ah + aRow0 * DD;
    const __half* srcA_l = Al + aRow0 * DD;
    const __half* srcB_h = Bh + bRow0 * DD;
    const __half* srcB_l = Bl + bRow0 * DD;

    const int m0 = (wid >> 2) * 64;
    const int n0 = (wid & 3) * 32;
    const int ltile = lane >> 3;
    const int rowInTile = (lane & 7) + ((ltile & 1) << 3);
    const int kk = ltile >> 1;
    const int lx = lane & 7;

    float acc[4][4][4];
    #pragma unroll
    for (int a = 0; a < 4; a++)
        #pragma unroll
        for (int b2 = 0; b2 < 4; b2++)
            #pragma unroll
            for (int c = 0; c < 4; c++) acc[a][b2][c] = 0.0f;

    const int nk = DD / KT;   // 8

    auto issue = [&](int i) {
        const uint32_t stg = sb + (uint32_t)(i & 1) * STAGE_BYTES;
        const int k0 = i * KT;
        #pragma unroll
        for (int t = 0; t < 4; t++) {
            const __half* base = (t == 0) ? srcA_h : (t == 1) ? srcA_l
                               : (t == 2) ? srcB_h : srcB_l;
            #pragma unroll
            for (int jj = 0; jj < 4; jj++) {
                int cid = tid + jj * 256;
                int row = cid >> 3, c = cid & 7;
                cp_async16(stg + t * TBYTES + row * 128 + ((c ^ (row & 7)) << 4),
                           base + (size_t)row * DD + k0 + c * 8);
            }
        }
        cp_commit();
    };

    issue(0);

    for (int i = 0; i < nk; i++) {
        if (i + 1 < nk) issue(i + 1);
        if (i + 1 < nk) cp_wait<1>(); else cp_wait<0>();
        __syncthreads();

        const uint32_t stg = sb + (uint32_t)(i & 1) * STAGE_BYTES;
        const uint32_t sAh = stg, sAl = stg + TBYTES, sBh = stg + 2 * TBYTES, sBl = stg + 3 * TBYTES;

        #pragma unroll
        for (int ks = 0; ks < 4; ks++) {
            const uint32_t swz = (uint32_t)(((ks * 2 + kk) ^ lx) << 4);
            uint32_t ah[4][4], al[4][4], bh[4][2], bl[4][2];
            #pragma unroll
            for (int mf = 0; mf < 4; mf++) {
                uint32_t off = (uint32_t)((m0 + mf * 16 + rowInTile) * 128) + swz;
                ldsm4(ah[mf], sAh + off);
                ldsm4(al[mf], sAl + off);
            }
            #pragma unroll
            for (int nh = 0; nh < 2; nh++) {
                uint32_t off = (uint32_t)((n0 + nh * 16 + rowInTile) * 128) + swz;
                uint32_t r[4], s[4];
                ldsm4(r, sBh + off);
                ldsm4(s, sBl + off);
                bh[nh * 2][0] = r[0]; bh[nh * 2][1] = r[2];
                bh[nh * 2 + 1][0] = r[1]; bh[nh * 2 + 1][1] = r[3];
                bl[nh * 2][0] = s[0]; bl[nh * 2][1] = s[2];
                bl[nh * 2 + 1][0] = s[1]; bl[nh * 2 + 1][1] = s[3];
            }
            #pragma unroll
            for (int mf = 0; mf < 4; mf++)
                #pragma unroll
                for (int nf = 0; nf < 4; nf++)
                    mma16816(acc[mf][nf], ah[mf], bh[nf]);
            #pragma unroll
            for (int mf = 0; mf < 4; mf++)
                #pragma unroll
                for (int nf = 0; nf < 4; nf++)
                    mma16816(acc[mf][nf], ah[mf], bl[nf]);
            #pragma unroll
            for (int mf = 0; mf < 4; mf++)
                #pragma unroll
                for (int nf = 0; nf < 4; nf++)
                    mma16816(acc[mf][nf], al[mf], bh[nf]);
        }
        __syncthreads();
    }

    const int rr = lane >> 2;
    const int cc = (lane & 3) * 2;
    #pragma unroll
    for (int mf = 0; mf < 4; mf++) {
        #pragma unroll
        for (int hf = 0; hf < 2; hf++) {
            long grow = aRow0 + m0 + mf * 16 + rr + hf * 8;
            float invd = 1.0f / denom[grow];
            #pragma unroll
            for (int nf = 0; nf < 4; nf++) {
                int gcol = colBlk + n0 + nf * 8 + cc;
                size_t gi = (size_t)grow * DD + gcol;
                float2 bv = *reinterpret_cast<const float2*>(&bias[gcol]);
                float2 o;
                o.x = fmaxf((acc[mf][nf][hf * 2 + 0] + 2.0f * bv.x) * invd, 0.0f);
                o.y = fmaxf((acc[mf][nf][hf * 2 + 1] + 2.0f * bv.y) * invd, 0.0f);
                *reinterpret_cast<float2*>(&OutF[gi]) = o;
            }
        }
    }
}

// ---------------- LayerNorm ----------------
__global__ void ln_kernel(const float* __restrict__ X, const float* __restrict__ g,
                          const float* __restrict__ b, float* __restrict__ out) {
    __shared__ float sh[32];
    const int row = blockIdx.x;
    const float* p = X + (size_t)row * DD;
    const int tid = threadIdx.x;
    float v0 = p[tid];
    float v1 = p[tid + 256];
    float mu = block_reduce_sum(v0 + v1, sh) * (1.0f / DD);
    float d0 = v0 - mu, d1 = v1 - mu;
    float var = block_reduce_sum(d0 * d0 + d1 * d1, sh) * (1.0f / DD);
    float r = rsqrtf(var + LN_EPS);
    out[(size_t)row * DD + tid] = d0 * r * g[tid] + b[tid];
    out[(size_t)row * DD + tid + 256] = d1 * r * g[tid + 256] + b[tid + 256];
}

__global__ void mask_kernel(const float* __restrict__ denom, const float* __restrict__ colsum,
                            float* __restrict__ out, int count) {
    int i = blockIdx.x * blockDim.x + threadIdx.x;
    if (i >= count) return;
    if (i < BB * NN) {
        float rs = denom[i] - 1.0f;
        out[i] = ((rs + colsum[i]) == 0.0f) ? 1.0f : 0.0f;
    } else {
        out[i] = 0.0f;
    }
}

// ---------------- launch ----------------
extern "C" void kernel_launch(void* const* d_in, const int* in_sizes, int n_in,
                              void* d_out, int out_size) {
    const float* adj = (const float*)d_in[0];
    const float* emb = (const float*)d_in[1];
    const float* W0w = (const float*)d_in[3];
    const float* W0b = (const float*)d_in[4];
    const float* W1w = (const float*)d_in[5];
    const float* W1b = (const float*)d_in[6];
    const float* lng = (const float*)d_in[7];
    const float* lnb = (const float*)d_in[8];
    float* out = (float*)d_out;

    float *denom, *colsum, *x;
    int8_t *adj0, *adj1, *xt0, *xt1;
    __half *yh, *yl, *w0h, *w0l, *w1h, *w1l;
    unsigned *amaxA, *amaxX;
    cudaGetSymbolAddress((void**)&denom, g_denom);
    cudaGetSymbolAddress((void**)&colsum, g_colsum);
    cudaGetSymbolAddress((void**)&x, g_x);
    cudaGetSymbolAddress((void**)&adj0, g_adj0);
    cudaGetSymbolAddress((void**)&adj1, g_adj1);
    cudaGetSymbolAddress((void**)&xt0, g_xT0);
    cudaGetSymbolAddress((void**)&xt1, g_xT1);
    cudaGetSymbolAddress((void**)&yh, g_y_h);
    cudaGetSymbolAddress((void**)&yl, g_y_l);
    cudaGetSymbolAddress((void**)&w0h, g_W0_h);
    cudaGetSymbolAddress((void**)&w0l, g_W0_l);
    cudaGetSymbolAddress((void**)&w1h, g_W1_h);
    cudaGetSymbolAddress((void**)&w1l, g_W1_l);
    cudaGetSymbolAddress((void**)&amaxA, g_amaxA);
    cudaGetSymbolAddress((void**)&amaxX, g_amaxX);

    cudaFuncSetAttribute(gemm1_i8, cudaFuncAttributeMaxDynamicSharedMemorySize, I8_SMEM);
    cudaFuncSetAttribute(gemm2_hmma, cudaFuncAttributeMaxDynamicSharedMemorySize, GEMM_SMEM);

    dim3 tg(DD / 32, NN / 32, BB);
    dim3 tb(32, 8);
    dim3 ga(8, BB);
    dim3 g1(DD / 128, NN / 128, BB);
    dim3 g2(DD / 128, (BB * NN) / 128, 1);
    int n4x = (BB * NN * DD) / 4;
    int w4 = (DD * DD) / 4;

    // L0   (launch #6 = gemm1_i8 -> ncu capture slot)
    zero2_kernel<<<(BB * NN + 255) / 256, 256>>>(colsum, amaxA, amaxX);       // 1
    adj_stats_kernel<<<ga, 256>>>(adj, denom, colsum, amaxA);                  // 2
    adj_quant_kernel<<<ga, 256>>>(adj, amaxA, adj0, adj1);                     // 3
    absmax_kernel<<<256, 256>>>(emb, n4x, amaxX);                              // 4
    transpose_quant<<<tg, tb>>>(emb, amaxX, xt0, xt1);                         // 5
    gemm1_i8<<<g1, 256, I8_SMEM>>>(adj0, adj1, xt0, xt1, emb, yh, yl, amaxA, amaxX); // 6
    split_kernel<<<(w4 + 255) / 256, 256>>>(W0w, w0h, w0l, w4);                // 7
    gemm2_hmma<<<g2, 256, GEMM_SMEM>>>(yh, yl, w0h, w0l, W0b, denom, x);       // 8
    // L1
    zerou_kernel<<<1, 1>>>(amaxX);                                             // 9
    absmax_kernel<<<256, 256>>>(x, n4x, amaxX);                                // 10
    transpose_quant<<<tg, tb>>>(x, amaxX, xt0, xt1);                           // 11
    gemm1_i8<<<g1, 256, I8_SMEM>>>(adj0, adj1, xt0, xt1, x, yh, yl, amaxA, amaxX);   // 12
    split_kernel<<<(w4 + 255) / 256, 256>>>(W1w, w1h, w1l, w4);                // 13
    gemm2_hmma<<<g2, 256, GEMM_SMEM>>>(yh, yl, w1h, w1l, W1b, denom, x);       // 14

    ln_kernel<<<BB * NN, 256>>>(x, lng, lnb, out);                             // 15

    int extra = out_size - BB * NN * DD;
    if (extra > 0) {
        mask_kernel<<<(extra + 255) / 256, 256>>>(denom, colsum,
                                                  out + (size_t)BB * NN * DD, extra);
    }
}

// round 6
// speedup vs baseline: 1.7188x; 1.7188x over previous
#include <cuda_runtime.h>
#include <cuda_fp16.h>
#include <cstdint>

#define BB 32
#define NN 1024
#define DD 512
#define LN_EPS 1e-5f

// ---------------- scratch (no allocations allowed) ----------------
__device__ float  g_denom[BB * NN];
__device__ float  g_colsum[BB * NN];
__device__ float  g_x[BB * NN * DD];                 // fp32 layer activations
__device__ __half g_adj_h[(size_t)BB * NN * NN];     // adj split
__device__ __half g_adj_l[(size_t)BB * NN * NN];
__device__ __half g_xT_h[(size_t)BB * DD * NN];      // X^T split (B operand of gemm1)
__device__ __half g_xT_l[(size_t)BB * DD * NN];
__device__ __half g_y_h[(size_t)BB * NN * DD];       // gemm1 output split (A of gemm2)
__device__ __half g_y_l[(size_t)BB * NN * DD];
__device__ __half g_W0_h[DD * DD];
__device__ __half g_W0_l[DD * DD];
__device__ __half g_W1_h[DD * DD];
__device__ __half g_W1_l[DD * DD];

// ---------------- PTX helpers (base sm_103-safe) ----------------
__device__ __forceinline__ uint32_t smem_u32(const void* p) {
    uint32_t a;
    asm("{ .reg .u64 t; cvta.to.shared.u64 t, %1; cvt.u32.u64 %0, t; }" : "=r"(a) : "l"(p));
    return a;
}
__device__ __forceinline__ void cp_async16(uint32_t dst, const void* src) {
    asm volatile("cp.async.cg.shared.global [%0], [%1], 16;" :: "r"(dst), "l"(src));
}
__device__ __forceinline__ void cp_commit() { asm volatile("cp.async.commit_group;" ::: "memory"); }
template <int N>
__device__ __forceinline__ void cp_wait() { asm volatile("cp.async.wait_group %0;" :: "n"(N) : "memory"); }

__device__ __forceinline__ void ldsm4(uint32_t* r, uint32_t addr) {
    asm volatile("ldmatrix.sync.aligned.m8n8.x4.shared.b16 {%0,%1,%2,%3}, [%4];"
                 : "=r"(r[0]), "=r"(r[1]), "=r"(r[2]), "=r"(r[3]) : "r"(addr));
}
__device__ __forceinline__ void mma16816(float* c, const uint32_t* a, const uint32_t* b) {
    asm volatile("mma.sync.aligned.m16n8k16.row.col.f32.f16.f16.f32 "
                 "{%0,%1,%2,%3}, {%4,%5,%6,%7}, {%8,%9}, {%0,%1,%2,%3};"
                 : "+f"(c[0]), "+f"(c[1]), "+f"(c[2]), "+f"(c[3])
                 : "r"(a[0]), "r"(a[1]), "r"(a[2]), "r"(a[3]), "r"(b[0]), "r"(b[1]));
}

// ---------------- reductions ----------------
__device__ __forceinline__ float block_reduce_sum(float v, float* sh) {
    __syncthreads();
    int tid = threadIdx.x;
    #pragma unroll
    for (int o = 16; o > 0; o >>= 1) v += __shfl_down_sync(0xffffffff, v, o);
    if ((tid & 31) == 0) sh[tid >> 5] = v;
    __syncthreads();
    if (tid < 32) {
        v = (tid < (int)(blockDim.x >> 5)) ? sh[tid] : 0.0f;
        #pragma unroll
        for (int o = 16; o > 0; o >>= 1) v += __shfl_down_sync(0xffffffff, v, o);
        if (tid == 0) sh[0] = v;
    }
    __syncthreads();
    return sh[0];
}

// ---------------- fused adj pass: rowsum+1 -> denom, colsum (atomic), fp16 split ----
__global__ void __launch_bounds__(256)
adj_pass_kernel(const float* __restrict__ adj, float* __restrict__ denom,
                float* __restrict__ colsum, __half* __restrict__ Ah,
                __half* __restrict__ Al) {
    __shared__ float rowacc[128];
    const int b = blockIdx.y;
    const int r0 = blockIdx.x * 128;
    const int tid = threadIdx.x;
    const int lane = tid & 31;
    const int col0 = tid * 4;

    for (int i = tid; i < 128; i += 256) rowacc[i] = 0.0f;
    __syncthreads();

    const float* src = adj + (size_t)b * NN * NN + (size_t)r0 * NN;
    __half* dh = Ah + (size_t)b * NN * NN + (size_t)r0 * NN;
    __half* dl = Al + (size_t)b * NN * NN + (size_t)r0 * NN;

    float cs0 = 0.f, cs1 = 0.f, cs2 = 0.f, cs3 = 0.f;

    for (int r = 0; r < 128; r++) {
        float4 v = *reinterpret_cast<const float4*>(&src[(size_t)r * NN + col0]);
        __half h0 = __float2half_rn(v.x), h1 = __float2half_rn(v.y);
        __half h2 = __float2half_rn(v.z), h3 = __float2half_rn(v.w);
        __half l0 = __float2half_rn(v.x - __half2float(h0));
        __half l1 = __float2half_rn(v.y - __half2float(h1));
        __half l2 = __float2half_rn(v.z - __half2float(h2));
        __half l3 = __float2half_rn(v.w - __half2float(h3));
        *reinterpret_cast<__half2*>(&dh[(size_t)r * NN + col0])     = __halves2half2(h0, h1);
        *reinterpret_cast<__half2*>(&dh[(size_t)r * NN + col0 + 2]) = __halves2half2(h2, h3);
        *reinterpret_cast<__half2*>(&dl[(size_t)r * NN + col0])     = __halves2half2(l0, l1);
        *reinterpret_cast<__half2*>(&dl[(size_t)r * NN + col0 + 2]) = __halves2half2(l2, l3);
        cs0 += v.x; cs1 += v.y; cs2 += v.z; cs3 += v.w;
        float s = (v.x + v.y) + (v.z + v.w);
        #pragma unroll
        for (int o = 16; o > 0; o >>= 1) s += __shfl_down_sync(0xffffffff, s, o);
        if (lane == 0) atomicAdd(&rowacc[r], s);
    }
    __syncthreads();
    if (tid < 128) denom[(size_t)b * NN + r0 + tid] = rowacc[tid] + 1.0f;
    float* cdst = colsum + (size_t)b * NN + col0;
    atomicAdd(cdst + 0, cs0);
    atomicAdd(cdst + 1, cs1);
    atomicAdd(cdst + 2, cs2);
    atomicAdd(cdst + 3, cs3);
}

__global__ void zero_kernel(float* __restrict__ p, int n) {
    int i = blockIdx.x * blockDim.x + threadIdx.x;
    if (i < n) p[i] = 0.0f;
}

__global__ void split_kernel(const float* __restrict__ src, __half* __restrict__ h,
                             __half* __restrict__ l, int n4) {
    int i = blockIdx.x * blockDim.x + threadIdx.x;
    if (i >= n4) return;
    float4 v = reinterpret_cast<const float4*>(src)[i];
    __half h0 = __float2half_rn(v.x), h1 = __float2half_rn(v.y);
    __half h2 = __float2half_rn(v.z), h3 = __float2half_rn(v.w);
    __half l0 = __float2half_rn(v.x - __half2float(h0));
    __half l1 = __float2half_rn(v.y - __half2float(h1));
    __half l2 = __float2half_rn(v.z - __half2float(h2));
    __half l3 = __float2half_rn(v.w - __half2float(h3));
    reinterpret_cast<__half2*>(h)[i * 2 + 0] = __halves2half2(h0, h1);
    reinterpret_cast<__half2*>(h)[i * 2 + 1] = __halves2half2(h2, h3);
    reinterpret_cast<__half2*>(l)[i * 2 + 0] = __halves2half2(l0, l1);
    reinterpret_cast<__half2*>(l)[i * 2 + 1] = __halves2half2(l2, l3);
}

__global__ void transpose_split(const float* __restrict__ x, __half* __restrict__ th,
                                __half* __restrict__ tl) {
    __shared__ float tile[32][33];
    int b = blockIdx.z;
    int m0 = blockIdx.y * 32, d0 = blockIdx.x * 32;
    const float* src = x + (size_t)b * NN * DD;
    int tx = threadIdx.x, ty = threadIdx.y;
    #pragma unroll
    for (int j = 0; j < 32; j += 8)
        tile[ty + j][tx] = src[(size_t)(m0 + ty + j) * DD + d0 + tx];
    __syncthreads();
    __half* dh = th + (size_t)b * DD * NN;
    __half* dl = tl + (size_t)b * DD * NN;
    #pragma unroll
    for (int j = 0; j < 32; j += 8) {
        float v = tile[tx][ty + j];
        __half h = __float2half_rn(v);
        __half l = __float2half_rn(v - __half2float(h));
        dh[(size_t)(d0 + ty + j) * NN + m0 + tx] = h;
        dl[(size_t)(d0 + ty + j) * NN + m0 + tx] = l;
    }
}

// ---------------- HMMA GEMM: 128x256 block tile, 512 threads, K-chunks of 64 ----
// D = Ah@Bh^T + Ah@Bl^T + Al@Bh^T (B stored K-major), fp32 acc in regs.
// 16 warps: wid>>3 -> M half (0/64), wid&7 -> N slice of 32.
#define KT 64
#define A_TB 16384                 // 128 rows x 128 B
#define B_TB 32768                 // 256 rows x 128 B
#define STAGE_BYTES (2 * A_TB + 2 * B_TB)   // 96 KB
#define GEMM_SMEM (2 * STAGE_BYTES)         // 192 KB

template <int KTOT, int EPI>
__global__ void __launch_bounds__(512, 1)
gemm_hmma(const __half* __restrict__ Ah, const __half* __restrict__ Al,
          const __half* __restrict__ Bh, const __half* __restrict__ Bl,
          const float* __restrict__ Xadd, __half* __restrict__ OutH, __half* __restrict__ OutL,
          const float* __restrict__ bias, const float* __restrict__ denom,
          float* __restrict__ OutF) {
    extern __shared__ char smem[];
    const uint32_t sb = smem_u32(smem);
    const int tid = threadIdx.x;
    const int wid = tid >> 5;
    const int lane = tid & 31;

    long aRow0, bRow0, outRow0;
    if (EPI == 1) {
        int b = blockIdx.z;
        aRow0 = (long)b * NN + blockIdx.y * 128;
        bRow0 = (long)b * DD + blockIdx.x * 256;
        outRow0 = aRow0;
    } else {
        aRow0 = (long)blockIdx.y * 128;
        bRow0 = (long)blockIdx.x * 256;
        outRow0 = aRow0;
    }
    const int colBlk = blockIdx.x * 256;

    const __half* srcA_h = Ah + aRow0 * KTOT;
    const __half* srcA_l = Al + aRow0 * KTOT;
    const __half* srcB_h = Bh + bRow0 * KTOT;
    const __half* srcB_l = Bl + bRow0 * KTOT;

    const int m0 = (wid >> 3) * 64;   // 0 / 64
    const int n0 = (wid & 7) * 32;    // 0..224

    const int ltile = lane >> 3;
    const int rowInTile = (lane & 7) + ((ltile & 1) << 3);
    const int kk = ltile >> 1;
    const int lx = lane & 7;

    float acc[4][4][4];
    #pragma unroll
    for (int a = 0; a < 4; a++)
        #pragma unroll
        for (int b2 = 0; b2 < 4; b2++)
            #pragma unroll
            for (int c = 0; c < 4; c++) acc[a][b2][c] = 0.0f;

    const int nk = KTOT / KT;

    auto issue = [&](int i) {
        const uint32_t stg = sb + (uint32_t)(i & 1) * STAGE_BYTES;
        const int k0 = i * KT;
        // A tiles: 128 rows each (1024 16B-chunks -> 2 per thread)
        #pragma unroll
        for (int t = 0; t < 2; t++) {
            const __half* base = (t == 0) ? srcA_h : srcA_l;
            #pragma unroll
            for (int jj = 0; jj < 2; jj++) {
                int cid = tid + jj * 512;          // 0..1023
                int row = cid >> 3, c = cid & 7;
                cp_async16(stg + t * A_TB + row * 128 + ((c ^ (row & 7)) << 4),
                           base + (size_t)row * KTOT + k0 + c * 8);
            }
        }
        // B tiles: 256 rows each (2048 chunks -> 4 per thread)
        #pragma unroll
        for (int t = 0; t < 2; t++) {
            const __half* base = (t == 0) ? srcB_h : srcB_l;
            #pragma unroll
            for (int jj = 0; jj < 4; jj++) {
                int cid = tid + jj * 512;          // 0..2047
                int row = cid >> 3, c = cid & 7;
                cp_async16(stg + 2 * A_TB + t * B_TB + row * 128 + ((c ^ (row & 7)) << 4),
                           base + (size_t)row * KTOT + k0 + c * 8);
            }
        }
        cp_commit();
    };

    issue(0);

    for (int i = 0; i < nk; i++) {
        if (i + 1 < nk) issue(i + 1);
        if (i + 1 < nk) cp_wait<1>(); else cp_wait<0>();
        __syncthreads();

        const uint32_t stg = sb + (uint32_t)(i & 1) * STAGE_BYTES;
        const uint32_t sAh = stg, sAl = stg + A_TB;
        const uint32_t sBh = stg + 2 * A_TB, sBl = stg + 2 * A_TB + B_TB;

        #pragma unroll
        for (int ks = 0; ks < 4; ks++) {
            const uint32_t swz = (uint32_t)(((ks * 2 + kk) ^ lx) << 4);
            uint32_t af[4][4], bh[4][2], bl[4][2];
            // phase 1: A-hi fragments + both B fragments
            #pragma unroll
            for (int mf = 0; mf < 4; mf++) {
                uint32_t off = (uint32_t)((m0 + mf * 16 + rowInTile) * 128) + swz;
                ldsm4(af[mf], sAh + off);
            }
            #pragma unroll
            for (int nh = 0; nh < 2; nh++) {
                uint32_t off = (uint32_t)((n0 + nh * 16 + rowInTile) * 128) + swz;
                uint32_t r[4], s[4];
                ldsm4(r, sBh + off);
                ldsm4(s, sBl + off);
                bh[nh * 2][0] = r[0]; bh[nh * 2][1] = r[2];
                bh[nh * 2 + 1][0] = r[1]; bh[nh * 2 + 1][1] = r[3];
                bl[nh * 2][0] = s[0]; bl[nh * 2][1] = s[2];
                bl[nh * 2 + 1][0] = s[1]; bl[nh * 2 + 1][1] = s[3];
            }
            #pragma unroll
            for (int mf = 0; mf < 4; mf++)
                #pragma unroll
                for (int nf = 0; nf < 4; nf++)
                    mma16816(acc[mf][nf], af[mf], bh[nf]);
            #pragma unroll
            for (int mf = 0; mf < 4; mf++)
                #pragma unroll
                for (int nf = 0; nf < 4; nf++)
                    mma16816(acc[mf][nf], af[mf], bl[nf]);
            // phase 2: overwrite fragments with A-lo
            #pragma unroll
            for (int mf = 0; mf < 4; mf++) {
                uint32_t off = (uint32_t)((m0 + mf * 16 + rowInTile) * 128) + swz;
                ldsm4(af[mf], sAl + off);
            }
            #pragma unroll
            for (int mf = 0; mf < 4; mf++)
                #pragma unroll
                for (int nf = 0; nf < 4; nf++)
                    mma16816(acc[mf][nf], af[mf], bh[nf]);
        }
        __syncthreads();
    }

    // ---- epilogue ----
    const int rr = lane >> 2;
    const int cc = (lane & 3) * 2;
    #pragma unroll
    for (int mf = 0; mf < 4; mf++) {
        #pragma unroll
        for (int hf = 0; hf < 2; hf++) {
            long grow = outRow0 + m0 + mf * 16 + rr + hf * 8;
            float invd = (EPI == 2) ? (1.0f / denom[grow]) : 0.0f;
            #pragma unroll
            for (int nf = 0; nf < 4; nf++) {
                int gcol = colBlk + n0 + nf * 8 + cc;
                size_t gi = (size_t)grow * DD + gcol;
                float v0 = acc[mf][nf][hf * 2 + 0];
                float v1 = acc[mf][nf][hf * 2 + 1];
                if (EPI == 1) {
                    float2 xv = *reinterpret_cast<const float2*>(&Xadd[gi]);
                    v0 += xv.x; v1 += xv.y;
                    __half h0 = __float2half_rn(v0), h1 = __float2half_rn(v1);
                    __half l0 = __float2half_rn(v0 - __half2float(h0));
                    __half l1 = __float2half_rn(v1 - __half2float(h1));
                    *reinterpret_cast<__half2*>(&OutH[gi]) = __halves2half2(h0, h1);
                    *reinterpret_cast<__half2*>(&OutL[gi]) = __halves2half2(l0, l1);
                } else {
                    float2 bv = *reinterpret_cast<const float2*>(&bias[gcol]);
                    float2 o;
                    o.x = fmaxf((v0 + 2.0f * bv.x) * invd, 0.0f);
                    o.y = fmaxf((v1 + 2.0f * bv.y) * invd, 0.0f);
                    *reinterpret_cast<float2*>(&OutF[gi]) = o;
                }
            }
        }
    }
}

// ---------------- LayerNorm ----------------
__global__ void ln_kernel(const float* __restrict__ X, const float* __restrict__ g,
                          const float* __restrict__ b, float* __restrict__ out) {
    __shared__ float sh[32];
    const int row = blockIdx.x;
    const float* p = X + (size_t)row * DD;
    const int tid = threadIdx.x;
    float v0 = p[tid];
    float v1 = p[tid + 256];
    float mu = block_reduce_sum(v0 + v1, sh) * (1.0f / DD);
    float d0 = v0 - mu, d1 = v1 - mu;
    float var = block_reduce_sum(d0 * d0 + d1 * d1, sh) * (1.0f / DD);
    float r = rsqrtf(var + LN_EPS);
    out[(size_t)row * DD + tid] = d0 * r * g[tid] + b[tid];
    out[(size_t)row * DD + tid + 256] = d1 * r * g[tid + 256] + b[tid + 256];
}

__global__ void mask_kernel(const float* __restrict__ denom, const float* __restrict__ colsum,
                            float* __restrict__ out, int count) {
    int i = blockIdx.x * blockDim.x + threadIdx.x;
    if (i >= count) return;
    if (i < BB * NN) {
        float rs = denom[i] - 1.0f;
        out[i] = ((rs + colsum[i]) == 0.0f) ? 1.0f : 0.0f;
    } else {
        out[i] = 0.0f;
    }
}

// ---------------- launch ----------------
extern "C" void kernel_launch(void* const* d_in, const int* in_sizes, int n_in,
                              void* d_out, int out_size) {
    const float* adj = (const float*)d_in[0];
    const float* emb = (const float*)d_in[1];
    const float* W0w = (const float*)d_in[3];
    const float* W0b = (const float*)d_in[4];
    const float* W1w = (const float*)d_in[5];
    const float* W1b = (const float*)d_in[6];
    const float* lng = (const float*)d_in[7];
    const float* lnb = (const float*)d_in[8];
    float* out = (float*)d_out;

    float *denom, *colsum, *x;
    __half *adjh, *adjl, *xth, *xtl, *yh, *yl, *w0h, *w0l, *w1h, *w1l;
    cudaGetSymbolAddress((void**)&denom, g_denom);
    cudaGetSymbolAddress((void**)&colsum, g_colsum);
    cudaGetSymbolAddress((void**)&x, g_x);
    cudaGetSymbolAddress((void**)&adjh, g_adj_h);
    cudaGetSymbolAddress((void**)&adjl, g_adj_l);
    cudaGetSymbolAddress((void**)&xth, g_xT_h);
    cudaGetSymbolAddress((void**)&xtl, g_xT_l);
    cudaGetSymbolAddress((void**)&yh, g_y_h);
    cudaGetSymbolAddress((void**)&yl, g_y_l);
    cudaGetSymbolAddress((void**)&w0h, g_W0_h);
    cudaGetSymbolAddress((void**)&w0l, g_W0_l);
    cudaGetSymbolAddress((void**)&w1h, g_W1_h);
    cudaGetSymbolAddress((void**)&w1l, g_W1_l);

    cudaFuncSetAttribute(gemm_hmma<1024, 1>, cudaFuncAttributeMaxDynamicSharedMemorySize, GEMM_SMEM);
    cudaFuncSetAttribute(gemm_hmma<512, 2>, cudaFuncAttributeMaxDynamicSharedMemorySize, GEMM_SMEM);

    dim3 tg(DD / 32, NN / 32, BB);
    dim3 tb(32, 8);
    dim3 ga(8, BB);
    dim3 g1(DD / 256, NN / 128, BB);        // (2, 8, 32)
    dim3 g2(DD / 256, (BB * NN) / 128, 1);  // (2, 256)
    int w4 = (DD * DD) / 4;

    zero_kernel<<<(BB * NN + 255) / 256, 256>>>(colsum, BB * NN);              // 1
    adj_pass_kernel<<<ga, 256>>>(adj, denom, colsum, adjh, adjl);              // 2
    transpose_split<<<tg, tb>>>(emb, xth, xtl);                                // 3
    gemm_hmma<1024, 1><<<g1, 512, GEMM_SMEM>>>(adjh, adjl, xth, xtl, emb, yh, yl,
                                               nullptr, nullptr, nullptr);     // 4
    split_kernel<<<(w4 + 255) / 256, 256>>>(W0w, w0h, w0l, w4);                // 5
    gemm_hmma<512, 2><<<g2, 512, GEMM_SMEM>>>(yh, yl, w0h, w0l, nullptr, nullptr, nullptr,
                                              W0b, denom, x);                  // 6
    split_kernel<<<(w4 + 255) / 256, 256>>>(W1w, w1h, w1l, w4);                // 7
    transpose_split<<<tg, tb>>>(x, xth, xtl);                                  // 8
    gemm_hmma<1024, 1><<<g1, 512, GEMM_SMEM>>>(adjh, adjl, xth, xtl, x, yh, yl,
                                               nullptr, nullptr, nullptr);     // 9
    gemm_hmma<512, 2><<<g2, 512, GEMM_SMEM>>>(yh, yl, w1h, w1l, nullptr, nullptr, nullptr,
                                              W1b, denom, x);                  // 10

    ln_kernel<<<BB * NN, 256>>>(x, lng, lnb, out);                             // 11

    int extra = out_size - BB * NN * DD;
    if (extra > 0) {
        mask_kernel<<<(extra + 255) / 256, 256>>>(denom, colsum,
                                                  out + (size_t)BB * NN * DD, extra);
    }
}